// round 2
// baseline (speedup 1.0000x reference)
#include <cuda_runtime.h>
#include <cuda_bf16.h>

// ---------------------------------------------------------------------------
// MPNEncoder (chemprop D-MPNN) on GB300.
// Pipeline:
//   inp = f_bonds @ W_i                      [100000 x 600]
//   message = relu(inp)
//   repeat 5x:
//     a_message[a] = sum_nb message[a2b[a,nb]]          [50000 x 600]
//     msg_in[b]   = a_message[b2a[b]] - message[b2revb[b]]
//     message = relu(inp + msg_in @ W_h)
//   a_message = gather-sum(message)
//   out = relu(concat(f_atoms, a_message) @ W_o + b_o)  [50000 x 600]
//
// GEMMs run on the fp32 CUDA-core path using packed fma.rn.f32x2 (Blackwell
// dual-fp32 pipe) with a 128x128x8 tile / 8x8 microtile SGEMM.
// ---------------------------------------------------------------------------

#define NATOMS 50000
#define NBONDS 100000
#define MAXNB  6
#define FATOM  133
#define FBOND  147
#define HIDDEN 600
#define DEPTH  6

// Scratch (allocation-free rule: device globals)
__device__ float g_inp  [NBONDS * HIDDEN];   // 240 MB
__device__ float g_msg  [NBONDS * HIDDEN];   // 240 MB
__device__ float g_amsg [NATOMS * HIDDEN];   // 120 MB
__device__ float g_msgin[NBONDS * HIDDEN];   // 240 MB

// ---------------------------------------------------------------------------
// Gather kernels (vectorized float4; 600 floats = 150 float4 per row)
// ---------------------------------------------------------------------------
#define ROW4 (HIDDEN / 4)   // 150

__global__ void gather_sum_kernel(const float4* __restrict__ msg,
                                  const int* __restrict__ a2b,
                                  float4* __restrict__ out)
{
    int tid = blockIdx.x * blockDim.x + threadIdx.x;
    const int total = NATOMS * ROW4;
    if (tid >= total) return;
    int a = tid / ROW4;
    int c = tid - a * ROW4;
    const int* nb = a2b + a * MAXNB;
    float4 s = make_float4(0.f, 0.f, 0.f, 0.f);
#pragma unroll
    for (int j = 0; j < MAXNB; j++) {
        float4 v = msg[nb[j] * ROW4 + c];
        s.x += v.x; s.y += v.y; s.z += v.z; s.w += v.w;
    }
    out[a * ROW4 + c] = s;
}

__global__ void build_msgin_kernel(const float4* __restrict__ amsg,
                                   const float4* __restrict__ msg,
                                   const int* __restrict__ b2a,
                                   const int* __restrict__ b2revb,
                                   float4* __restrict__ out)
{
    int tid = blockIdx.x * blockDim.x + threadIdx.x;
    const int total = NBONDS * ROW4;
    if (tid >= total) return;
    int b = tid / ROW4;
    int c = tid - b * ROW4;
    float4 s = amsg[b2a[b] * ROW4 + c];
    float4 r = msg[b2revb[b] * ROW4 + c];
    s.x -= r.x; s.y -= r.y; s.z -= r.z; s.w -= r.w;
    out[b * ROW4 + c] = s;
}

// ---------------------------------------------------------------------------
// SGEMM: C = relu(A @ B [+ addend] [+ bias]); optional pre-activation store.
// A: [M,K] row-major (MODE 1: A is concat(Aa[M,KA], A[M,K-KA])).
// B: [K,N] row-major. 128x128x8 tiles, 256 threads, 8x8 microtiles,
// packed f32x2 FMAs (2 fp32 FMA lanes per instruction on sm_103a).
// ---------------------------------------------------------------------------
#define BM 128
#define BN 128
#define BK 8
#define GT 256

__device__ __forceinline__ unsigned long long pack_dup(float a)
{
    unsigned long long r;
    unsigned int ai = __float_as_uint(a);
    asm("mov.b64 %0, {%1, %1};" : "=l"(r) : "r"(ai));
    return r;
}

#define FMA2(d, a, b) \
    asm("fma.rn.f32x2 %0, %1, %2, %0;" : "+l"(d) : "l"(a), "l"(b))

template <int MODE>
__global__ __launch_bounds__(GT, 2) void gemm_fused(
    const float* __restrict__ A,      // MODE0: [M,K].  MODE1: tail part [M, K-KA]
    const float* __restrict__ Aa,     // MODE1: head part [M, KA]
    int KA,
    const float* __restrict__ B,      // [K,N]
    const float* __restrict__ addend, // [M,N] or null
    const float* __restrict__ bias,   // [N]   or null
    float* __restrict__ outRelu,      // [M,N]
    float* __restrict__ outPre,       // [M,N] or null
    int M, int N, int K)
{
    __shared__ __align__(16) float As[BK][BM + 4];  // +4 pad: conflict-free STS, 16B-aligned rows
    __shared__ __align__(16) float Bs[BK][BN];

    const int tid = threadIdx.x;
    const int tx  = tid & 15;   // 16 col-tiles of 8
    const int ty  = tid >> 4;   // 16 row-tiles of 8
    const int m0  = blockIdx.y * BM;
    const int n0  = blockIdx.x * BN;

    auto loadA = [&](int m, int k) -> float {
        if (m >= M || k >= K) return 0.0f;
        if (MODE == 0) return A[m * K + k];
        return (k < KA) ? Aa[m * KA + k] : A[m * (K - KA) + (k - KA)];
    };
    auto loadB = [&](int k, int n) -> float {
        if (k >= K || n >= N) return 0.0f;
        return B[k * N + n];
    };

    // prologue: tile 0 into smem
#pragma unroll
    for (int p = 0; p < 4; p++) {
        int i = tid + GT * p;
        As[i & 7][i >> 3] = loadA(m0 + (i >> 3), i & 7);
    }
#pragma unroll
    for (int p = 0; p < 4; p++) {
        int i = tid + GT * p;
        Bs[i >> 7][i & 127] = loadB(i >> 7, n0 + (i & 127));
    }
    __syncthreads();

    unsigned long long acc[8][4];
#pragma unroll
    for (int i = 0; i < 8; i++)
#pragma unroll
        for (int j = 0; j < 4; j++) acc[i][j] = 0ull;

    const int ntiles = (K + BK - 1) / BK;
    float aPre[4], bPre[4];

    for (int t = 0; t < ntiles; t++) {
        const bool pf = (t + 1 < ntiles);
        const int kb = (t + 1) * BK;
        if (pf) {  // register prefetch of next tile (hides global latency)
#pragma unroll
            for (int p = 0; p < 4; p++) {
                int i = tid + GT * p;
                aPre[p] = loadA(m0 + (i >> 3), kb + (i & 7));
                bPre[p] = loadB(kb + (i >> 7), n0 + (i & 127));
            }
        }
#pragma unroll
        for (int kk = 0; kk < BK; kk++) {
            const float4 a0 = *(const float4*)&As[kk][ty * 8];
            const float4 a1 = *(const float4*)&As[kk][ty * 8 + 4];
            const ulonglong2 b0 = *(const ulonglong2*)&Bs[kk][tx * 8];
            const ulonglong2 b1 = *(const ulonglong2*)&Bs[kk][tx * 8 + 4];
            const float af[8] = {a0.x, a0.y, a0.z, a0.w, a1.x, a1.y, a1.z, a1.w};
#pragma unroll
            for (int i = 0; i < 8; i++) {
                unsigned long long ap = pack_dup(af[i]);
                FMA2(acc[i][0], ap, b0.x);
                FMA2(acc[i][1], ap, b0.y);
                FMA2(acc[i][2], ap, b1.x);
                FMA2(acc[i][3], ap, b1.y);
            }
        }
        if (pf) {
            __syncthreads();
#pragma unroll
            for (int p = 0; p < 4; p++) {
                int i = tid + GT * p;
                As[i & 7][i >> 3]   = aPre[p];
                Bs[i >> 7][i & 127] = bPre[p];
            }
            __syncthreads();
        }
    }

    // epilogue
#pragma unroll
    for (int i = 0; i < 8; i++) {
        int row = m0 + ty * 8 + i;
        if (row >= M) break;
        float v[8];
#pragma unroll
        for (int j = 0; j < 4; j++) {
            float lo, hi;
            asm("mov.b64 {%0, %1}, %2;" : "=f"(lo), "=f"(hi) : "l"(acc[i][j]));
            v[2 * j] = lo;
            v[2 * j + 1] = hi;
        }
#pragma unroll
        for (int j = 0; j < 8; j++) {
            int col = n0 + tx * 8 + j;
            if (col < N) {
                float x = v[j];
                if (addend) x += addend[row * N + col];
                if (bias)   x += bias[col];
                if (outPre) outPre[row * N + col] = x;
                outRelu[row * N + col] = fmaxf(x, 0.0f);
            }
        }
    }
}

// ---------------------------------------------------------------------------
// Launch
// ---------------------------------------------------------------------------
static inline int cdiv(int a, int b) { return (a + b - 1) / b; }

extern "C" void kernel_launch(void* const* d_in, const int* in_sizes, int n_in,
                              void* d_out, int out_size)
{
    const float* f_atoms = (const float*)d_in[0];
    const float* f_bonds = (const float*)d_in[1];
    const int*   a2b     = (const int*)d_in[2];
    const int*   b2a     = (const int*)d_in[3];
    const int*   b2revb  = (const int*)d_in[4];
    const float* W_i     = (const float*)d_in[5];
    const float* W_h     = (const float*)d_in[6];
    const float* W_o     = (const float*)d_in[7];
    const float* b_o     = (const float*)d_in[8];
    float*       out     = (float*)d_out;

    // Symbol-address lookups: host-side queries, capture-safe (no work enqueued,
    // no allocation).
    float *inp, *msg, *amsg, *msgin;
    cudaGetSymbolAddress((void**)&inp,   g_inp);
    cudaGetSymbolAddress((void**)&msg,   g_msg);
    cudaGetSymbolAddress((void**)&amsg,  g_amsg);
    cudaGetSymbolAddress((void**)&msgin, g_msgin);

    const dim3 bdim(GT);
    const dim3 gBond(cdiv(HIDDEN, BN), cdiv(NBONDS, BM));   // (5, 782)
    const dim3 gAtom(cdiv(HIDDEN, BN), cdiv(NATOMS, BM));   // (5, 391)
    const int gsBlocks = cdiv(NATOMS * ROW4, 256);
    const int bmBlocks = cdiv(NBONDS * ROW4, 256);

    // inp = f_bonds @ W_i ; message = relu(inp)
    gemm_fused<0><<<gBond, bdim>>>(f_bonds, nullptr, 0, W_i,
                                   nullptr, nullptr, msg, inp,
                                   NBONDS, HIDDEN, FBOND);

    for (int d = 0; d < DEPTH - 1; d++) {
        gather_sum_kernel<<<gsBlocks, 256>>>((const float4*)msg, a2b,
                                             (float4*)amsg);
        build_msgin_kernel<<<bmBlocks, 256>>>((const float4*)amsg,
                                              (const float4*)msg,
                                              b2a, b2revb, (float4*)msgin);
        // message = relu(inp + msgin @ W_h)
        gemm_fused<0><<<gBond, bdim>>>(msgin, nullptr, 0, W_h,
                                       inp, nullptr, msg, nullptr,
                                       NBONDS, HIDDEN, HIDDEN);
    }

    gather_sum_kernel<<<gsBlocks, 256>>>((const float4*)msg, a2b,
                                         (float4*)amsg);
    // out = relu(concat(f_atoms, a_message) @ W_o + b_o)
    gemm_fused<1><<<gAtom, bdim>>>(amsg, f_atoms, FATOM, W_o,
                                   nullptr, b_o, out, nullptr,
                                   NATOMS, HIDDEN, FATOM + HIDDEN);
}

// round 9
// speedup vs baseline: 2.4668x; 2.4668x over previous
#include <cuda_runtime.h>
#include <cuda_bf16.h>
#include <stdint.h>

// ---------------------------------------------------------------------------
// MPNEncoder (chemprop D-MPNN) on GB300 — legacy tensor path (mma.sync bf16).
//
// The harness PTX-targets compute_103 (no 'a'), so tcgen05/TMEM is
// unavailable. We use baseline-ISA mma.sync.m16n8k16 bf16 (HMMA) instead.
//
// fp32 GEMM emulated as: x = hi + lo (bf16 pair),
//   A@W ≈ A_hi@W_hi + A_lo@W_hi + A_hi@W_lo   (fp32 accumulate)
//
// GEMM: 128x128 CTA tile, 8 warps (4 M x 2 N), 32x64 warp tile, BK=32,
// 2-stage cp.async double buffer, ldmatrix fragments.
// ---------------------------------------------------------------------------

#define NATOMS 50000
#define NBONDS 100000
#define MAXNB  6
#define FATOM  133
#define FBOND  147
#define HIDDEN 600
#define DEPTH  6
#define NCOLS  600
#define NROWPAD 640     // W^T rows padded to 5 tiles of 128

#define KPAD_I 160      // 147 -> 5 chunks of 32
#define KPAD_H 608      // 600 -> 19 chunks
#define KPAD_O 736      // 733 -> 23 chunks

// ---------------- scratch (allocation-free rule: device globals) -----------
__device__ float g_inp [NBONDS * HIDDEN];
__device__ float g_msg [NBONDS * HIDDEN];
__device__ float g_amsg[NATOMS * HIDDEN];
__device__ __nv_bfloat16 g_Ahi[NBONDS * KPAD_O];
__device__ __nv_bfloat16 g_Alo[NBONDS * KPAD_O];
__device__ __nv_bfloat16 g_WiThi[NROWPAD * KPAD_I];
__device__ __nv_bfloat16 g_WiTlo[NROWPAD * KPAD_I];
__device__ __nv_bfloat16 g_WhThi[NROWPAD * KPAD_H];
__device__ __nv_bfloat16 g_WhTlo[NROWPAD * KPAD_H];
__device__ __nv_bfloat16 g_WoThi[NROWPAD * KPAD_O];
__device__ __nv_bfloat16 g_WoTlo[NROWPAD * KPAD_O];

// ---------------- helpers ---------------------------------------------------
__device__ __forceinline__ uint32_t smem_u32(const void* p)
{
    uint32_t a;
    asm("{ .reg .u64 t; cvta.to.shared.u64 t, %1; cvt.u32.u64 %0, t; }"
        : "=r"(a) : "l"(p));
    return a;
}

__device__ __forceinline__ void cp16(uint32_t s, const void* g)
{
    asm volatile("cp.async.cg.shared.global [%0], [%1], 16;"
                 :: "r"(s), "l"(g));
}

__device__ __forceinline__ void cp_commit()
{
    asm volatile("cp.async.commit_group;" ::: "memory");
}

#define LDSM_X4(r0, r1, r2, r3, a) \
    asm volatile("ldmatrix.sync.aligned.m8n8.x4.shared.b16 {%0,%1,%2,%3}, [%4];" \
                 : "=r"(r0), "=r"(r1), "=r"(r2), "=r"(r3) : "r"(a))

#define LDSM_X2(r0, r1, a) \
    asm volatile("ldmatrix.sync.aligned.m8n8.x2.shared.b16 {%0,%1}, [%2];" \
                 : "=r"(r0), "=r"(r1) : "r"(a))

#define MMA_BF16(d, a, b) \
    asm volatile("mma.sync.aligned.m16n8k16.row.col.f32.bf16.bf16.f32 " \
                 "{%0,%1,%2,%3}, {%4,%5,%6,%7}, {%8,%9}, {%0,%1,%2,%3};" \
                 : "+f"((d)[0]), "+f"((d)[1]), "+f"((d)[2]), "+f"((d)[3]) \
                 : "r"((a)[0]), "r"((a)[1]), "r"((a)[2]), "r"((a)[3]), \
                   "r"((b)[0]), "r"((b)[1]))

__device__ __forceinline__ void split2(float v, unsigned short& h, unsigned short& l)
{
    __nv_bfloat16 hb = __float2bfloat16(v);
    float r = v - __bfloat162float(hb);
    __nv_bfloat16 lb = __float2bfloat16(r);
    h = __bfloat16_as_ushort(hb);
    l = __bfloat16_as_ushort(lb);
}

// ---------------- gather / split kernels ------------------------------------
#define ROW4 (HIDDEN / 4)   // 150

__global__ void gather_sum_kernel(const float4* __restrict__ msg,
                                  const int* __restrict__ a2b,
                                  float4* __restrict__ out)
{
    int tid = blockIdx.x * blockDim.x + threadIdx.x;
    const int total = NATOMS * ROW4;
    if (tid >= total) return;
    int a = tid / ROW4;
    int c = tid - a * ROW4;
    const int* nb = a2b + a * MAXNB;
    float4 s = make_float4(0.f, 0.f, 0.f, 0.f);
#pragma unroll
    for (int j = 0; j < MAXNB; j++) {
        float4 v = msg[(size_t)nb[j] * ROW4 + c];
        s.x += v.x; s.y += v.y; s.z += v.z; s.w += v.w;
    }
    out[(size_t)a * ROW4 + c] = s;
}

// msgin = amsg[b2a[b]] - msg[b2revb[b]]  -> split bf16 hi/lo, K padded
__global__ void build_msgin_split(const float4* __restrict__ amsg,
                                  const float4* __restrict__ msg,
                                  const int* __restrict__ b2a,
                                  const int* __restrict__ b2revb,
                                  __nv_bfloat16* __restrict__ Ahi,
                                  __nv_bfloat16* __restrict__ Alo)
{
    int tid = blockIdx.x * blockDim.x + threadIdx.x;
    const int C4 = KPAD_H / 4;                       // 152
    const int total = NBONDS * C4;
    if (tid >= total) return;
    int b  = tid / C4;
    int c4 = tid - b * C4;
    float4 d = make_float4(0.f, 0.f, 0.f, 0.f);
    if (c4 < ROW4) {
        float4 s = amsg[(size_t)b2a[b]    * ROW4 + c4];
        float4 r = msg [(size_t)b2revb[b] * ROW4 + c4];
        d.x = s.x - r.x; d.y = s.y - r.y; d.z = s.z - r.z; d.w = s.w - r.w;
    }
    unsigned short h0, h1, h2, h3, l0, l1, l2, l3;
    split2(d.x, h0, l0); split2(d.y, h1, l1);
    split2(d.z, h2, l2); split2(d.w, h3, l3);
    uint2 hv, lv;
    hv.x = (uint32_t)h0 | ((uint32_t)h1 << 16);
    hv.y = (uint32_t)h2 | ((uint32_t)h3 << 16);
    lv.x = (uint32_t)l0 | ((uint32_t)l1 << 16);
    lv.y = (uint32_t)l2 | ((uint32_t)l3 << 16);
    size_t off = (size_t)b * KPAD_H + (size_t)c4 * 4;
    *(uint2*)(Ahi + off) = hv;
    *(uint2*)(Alo + off) = lv;
}

__global__ void split_bonds_kernel(const float* __restrict__ fb,
                                   __nv_bfloat16* __restrict__ Ahi,
                                   __nv_bfloat16* __restrict__ Alo)
{
    int tid = blockIdx.x * blockDim.x + threadIdx.x;
    const int total = NBONDS * KPAD_I;
    if (tid >= total) return;
    int b = tid / KPAD_I;
    int k = tid - b * KPAD_I;
    float v = (k < FBOND) ? fb[(size_t)b * FBOND + k] : 0.f;
    unsigned short h, l;
    split2(v, h, l);
    Ahi[tid] = __ushort_as_bfloat16(h);
    Alo[tid] = __ushort_as_bfloat16(l);
}

__global__ void concat_split_kernel(const float* __restrict__ fa,
                                    const float* __restrict__ amsg,
                                    __nv_bfloat16* __restrict__ Ahi,
                                    __nv_bfloat16* __restrict__ Alo)
{
    int tid = blockIdx.x * blockDim.x + threadIdx.x;
    const int total = NATOMS * KPAD_O;
    if (tid >= total) return;
    int a = tid / KPAD_O;
    int k = tid - a * KPAD_O;
    float v = 0.f;
    if (k < FATOM)               v = fa[(size_t)a * FATOM + k];
    else if (k < FATOM + HIDDEN) v = amsg[(size_t)a * HIDDEN + (k - FATOM)];
    unsigned short h, l;
    split2(v, h, l);
    Ahi[tid] = __ushort_as_bfloat16(h);
    Alo[tid] = __ushort_as_bfloat16(l);
}

// W [K,600] row-major -> W^T split bf16, [640][ldT], zero-padded
__global__ void prep_w_kernel(const float* __restrict__ W, int K, int ldT,
                              __nv_bfloat16* __restrict__ Thi,
                              __nv_bfloat16* __restrict__ Tlo)
{
    int tid = blockIdx.x * blockDim.x + threadIdx.x;
    const int total = NROWPAD * ldT;
    if (tid >= total) return;
    int n = tid / ldT;
    int k = tid - n * ldT;
    float v = (n < NCOLS && k < K) ? W[(size_t)k * NCOLS + n] : 0.f;
    unsigned short h, l;
    split2(v, h, l);
    Thi[tid] = __ushort_as_bfloat16(h);
    Tlo[tid] = __ushort_as_bfloat16(l);
}

// ---------------- tensor-core GEMM (mma.sync bf16, split hi/lo) -------------
// grid = (5 N-tiles, ceil(M/128)); 256 threads = 8 warps (4 M x 2 N).
#define RS        40            // smem row stride in bf16 (80B, LDSM-conflict-free)
#define TILE_B    (128 * RS * 2)   // 10240 B
#define OFF_AHI   0
#define OFF_ALO   (TILE_B)
#define OFF_BHI   (2 * TILE_B)
#define OFF_BLO   (3 * TILE_B)
#define STAGE_B   (4 * TILE_B)     // 40960 B
#define SMEM_TOT  (2 * STAGE_B)    // 81920 B

__global__ __launch_bounds__(256)
void gemm_tc(const __nv_bfloat16* __restrict__ Ahi,
             const __nv_bfloat16* __restrict__ Alo,
             const __nv_bfloat16* __restrict__ Bhi,
             const __nv_bfloat16* __restrict__ Blo,
             const float* __restrict__ addend,
             const float* __restrict__ bias,
             float* __restrict__ outRelu,
             float* __restrict__ outPre,
             int M, int KC, int ld)
{
    extern __shared__ char smem[];
    const uint32_t sb = smem_u32(smem);
    const int tid  = threadIdx.x;
    const int lane = tid & 31;
    const int wid  = tid >> 5;
    const int wm   = wid & 3;          // 4 warps along M (32 rows each)
    const int wn   = wid >> 2;         // 2 warps along N (64 cols each)
    const int m0   = blockIdx.y * 128;
    const int n0   = blockIdx.x * 128;

    // async loader: stage s <- K-chunk kc
    auto issue = [&](int kc, int s) {
        const uint32_t sbase = sb + s * STAGE_B;
#pragma unroll
        for (int p = 0; p < 2; p++) {
            int slot = tid + 256 * p;         // 0..511
            int row  = slot >> 2;
            int j    = slot & 3;
            uint32_t soff = (uint32_t)row * (RS * 2) + j * 16;
            int arow = m0 + row;
            if (arow >= M) arow = M - 1;      // clamp (garbage rows masked later)
            size_t ga = (size_t)arow * ld + (size_t)kc * 32 + j * 8;
            cp16(sbase + OFF_AHI + soff, Ahi + ga);
            cp16(sbase + OFF_ALO + soff, Alo + ga);
            size_t gb = (size_t)(n0 + row) * ld + (size_t)kc * 32 + j * 8;
            cp16(sbase + OFF_BHI + soff, Bhi + gb);
            cp16(sbase + OFF_BLO + soff, Blo + gb);
        }
        cp_commit();
    };

    float acc[2][8][4];
#pragma unroll
    for (int mt = 0; mt < 2; mt++)
#pragma unroll
        for (int nt = 0; nt < 8; nt++)
#pragma unroll
            for (int q = 0; q < 4; q++) acc[mt][nt][q] = 0.f;

    issue(0, 0);

    // lane-invariant fragment address pieces
    const int aRow = wm * 32 + (lane & 15);
    const int aCol = (lane >> 4) << 3;
    const int bRow = wn * 64 + (lane & 7);
    const int bCol = ((lane >> 3) & 1) << 3;

    for (int kc = 0; kc < KC; kc++) {
        if (kc + 1 < KC) {
            issue(kc + 1, (kc + 1) & 1);
            asm volatile("cp.async.wait_group 1;" ::: "memory");
        } else {
            asm volatile("cp.async.wait_group 0;" ::: "memory");
        }
        __syncthreads();

        const uint32_t st = sb + (kc & 1) * STAGE_B;
        const uint32_t aAddrBase = st + (uint32_t)aRow * (RS * 2) + aCol * 2;
        const uint32_t bAddrBase = st + (uint32_t)bRow * (RS * 2) + bCol * 2;

#pragma unroll
        for (int ks = 0; ks < 32; ks += 16) {
            uint32_t ahi[2][4], alo[2][4], bfr[8][2];
#pragma unroll
            for (int mt = 0; mt < 2; mt++) {
                uint32_t a = aAddrBase + OFF_AHI + ((uint32_t)mt * 16 * RS + ks) * 2;
                LDSM_X4(ahi[mt][0], ahi[mt][1], ahi[mt][2], ahi[mt][3], a);
            }
#pragma unroll
            for (int nt = 0; nt < 8; nt++) {
                uint32_t b = bAddrBase + OFF_BHI + ((uint32_t)nt * 8 * RS + ks) * 2;
                LDSM_X2(bfr[nt][0], bfr[nt][1], b);
            }
            // product 1: hi * hi
#pragma unroll
            for (int mt = 0; mt < 2; mt++)
#pragma unroll
                for (int nt = 0; nt < 8; nt++)
                    MMA_BF16(acc[mt][nt], ahi[mt], bfr[nt]);
            // product 2: lo * hi
#pragma unroll
            for (int mt = 0; mt < 2; mt++) {
                uint32_t a = aAddrBase + OFF_ALO + ((uint32_t)mt * 16 * RS + ks) * 2;
                LDSM_X4(alo[mt][0], alo[mt][1], alo[mt][2], alo[mt][3], a);
            }
#pragma unroll
            for (int mt = 0; mt < 2; mt++)
#pragma unroll
                for (int nt = 0; nt < 8; nt++)
                    MMA_BF16(acc[mt][nt], alo[mt], bfr[nt]);
            // product 3: hi * lo
#pragma unroll
            for (int nt = 0; nt < 8; nt++) {
                uint32_t b = bAddrBase + OFF_BLO + ((uint32_t)nt * 8 * RS + ks) * 2;
                LDSM_X2(bfr[nt][0], bfr[nt][1], b);
            }
#pragma unroll
            for (int mt = 0; mt < 2; mt++)
#pragma unroll
                for (int nt = 0; nt < 8; nt++)
                    MMA_BF16(acc[mt][nt], ahi[mt], bfr[nt]);
        }
        __syncthreads();
    }

    // epilogue: d-frag thread t -> rows t/4, t/4+8; cols (t%4)*2, +1
    const int rBase = m0 + wm * 32 + (lane >> 2);
    const int cBase = n0 + wn * 64 + (lane & 3) * 2;
#pragma unroll
    for (int mt = 0; mt < 2; mt++) {
#pragma unroll
        for (int half = 0; half < 2; half++) {
            int row = rBase + mt * 16 + half * 8;
            if (row >= M) continue;
            const size_t rb = (size_t)row * NCOLS;
#pragma unroll
            for (int nt = 0; nt < 8; nt++) {
                int col = cBase + nt * 8;
                if (col >= NCOLS) continue;
                float x0 = acc[mt][nt][half * 2 + 0];
                float x1 = acc[mt][nt][half * 2 + 1];
                if (addend) {
                    float2 a = *(const float2*)(addend + rb + col);
                    x0 += a.x; x1 += a.y;
                }
                if (bias) {
                    float2 bv = *(const float2*)(bias + col);
                    x0 += bv.x; x1 += bv.y;
                }
                if (outPre) {
                    float2 pv = make_float2(x0, x1);
                    *(float2*)(outPre + rb + col) = pv;
                }
                float2 rv = make_float2(fmaxf(x0, 0.f), fmaxf(x1, 0.f));
                *(float2*)(outRelu + rb + col) = rv;
            }
        }
    }
}

// ---------------- launch ----------------------------------------------------
static inline int cdiv(int a, int b) { return (a + b - 1) / b; }

extern "C" void kernel_launch(void* const* d_in, const int* in_sizes, int n_in,
                              void* d_out, int out_size)
{
    const float* f_atoms = (const float*)d_in[0];
    const float* f_bonds = (const float*)d_in[1];
    const int*   a2b     = (const int*)d_in[2];
    const int*   b2a     = (const int*)d_in[3];
    const int*   b2revb  = (const int*)d_in[4];
    const float* W_i     = (const float*)d_in[5];
    const float* W_h     = (const float*)d_in[6];
    const float* W_o     = (const float*)d_in[7];
    const float* b_o     = (const float*)d_in[8];
    float*       out     = (float*)d_out;

    float *inp, *msg, *amsg;
    __nv_bfloat16 *Ahi, *Alo, *WiThi, *WiTlo, *WhThi, *WhTlo, *WoThi, *WoTlo;
    cudaGetSymbolAddress((void**)&inp,   g_inp);
    cudaGetSymbolAddress((void**)&msg,   g_msg);
    cudaGetSymbolAddress((void**)&amsg,  g_amsg);
    cudaGetSymbolAddress((void**)&Ahi,   g_Ahi);
    cudaGetSymbolAddress((void**)&Alo,   g_Alo);
    cudaGetSymbolAddress((void**)&WiThi, g_WiThi);
    cudaGetSymbolAddress((void**)&WiTlo, g_WiTlo);
    cudaGetSymbolAddress((void**)&WhThi, g_WhThi);
    cudaGetSymbolAddress((void**)&WhTlo, g_WhTlo);
    cudaGetSymbolAddress((void**)&WoThi, g_WoThi);
    cudaGetSymbolAddress((void**)&WoTlo, g_WoTlo);

    cudaFuncSetAttribute(gemm_tc, cudaFuncAttributeMaxDynamicSharedMemorySize,
                         SMEM_TOT);

    // weight prep (tiny)
    prep_w_kernel<<<cdiv(NROWPAD * KPAD_I, 256), 256>>>(W_i, FBOND, KPAD_I, WiThi, WiTlo);
    prep_w_kernel<<<cdiv(NROWPAD * KPAD_H, 256), 256>>>(W_h, HIDDEN, KPAD_H, WhThi, WhTlo);
    prep_w_kernel<<<cdiv(NROWPAD * KPAD_O, 256), 256>>>(W_o, FATOM + HIDDEN, KPAD_O, WoThi, WoTlo);

    const dim3 gBond(5, cdiv(NBONDS, 128));   // (5, 782) — x fastest: A reuse in L2
    const dim3 gAtom(5, cdiv(NATOMS, 128));   // (5, 391)

    // inp = f_bonds @ W_i ; msg = relu(inp)
    split_bonds_kernel<<<cdiv(NBONDS * KPAD_I, 256), 256>>>(f_bonds, Ahi, Alo);
    gemm_tc<<<gBond, 256, SMEM_TOT>>>(Ahi, Alo, WiThi, WiTlo,
                                      nullptr, nullptr, msg, inp,
                                      NBONDS, KPAD_I / 32, KPAD_I);

    const int gsBlocks = cdiv(NATOMS * ROW4, 256);
    const int bmBlocks = cdiv(NBONDS * (KPAD_H / 4), 256);

    for (int d = 0; d < DEPTH - 1; d++) {
        gather_sum_kernel<<<gsBlocks, 256>>>((const float4*)msg, a2b, (float4*)amsg);
        build_msgin_split<<<bmBlocks, 256>>>((const float4*)amsg, (const float4*)msg,
                                             b2a, b2revb, Ahi, Alo);
        // msg = relu(inp + msgin @ W_h)
        gemm_tc<<<gBond, 256, SMEM_TOT>>>(Ahi, Alo, WhThi, WhTlo,
                                          inp, nullptr, msg, nullptr,
                                          NBONDS, KPAD_H / 32, KPAD_H);
    }

    gather_sum_kernel<<<gsBlocks, 256>>>((const float4*)msg, a2b, (float4*)amsg);
    concat_split_kernel<<<cdiv(NATOMS * KPAD_O, 256), 256>>>(f_atoms, amsg, Ahi, Alo);
    // out = relu(concat(f_atoms, amsg) @ W_o + b_o)
    gemm_tc<<<gAtom, 256, SMEM_TOT>>>(Ahi, Alo, WoThi, WoTlo,
                                      nullptr, b_o, out, nullptr,
                                      NATOMS, KPAD_O / 32, KPAD_O);
}

// round 12
// speedup vs baseline: 2.5104x; 1.0177x over previous
#include <cuda_runtime.h>
#include <cuda_bf16.h>
#include <stdint.h>

// ---------------------------------------------------------------------------
// MPNEncoder (chemprop D-MPNN) on GB300 — mma.sync bf16 split hi/lo GEMM.
// R10: fused gather+msgin+split (amsg round-trip eliminated in mainloop),
//      vectorized bf16 split stores.
// ---------------------------------------------------------------------------

#define NATOMS 50000
#define NBONDS 100000
#define MAXNB  6
#define FATOM  133
#define FBOND  147
#define HIDDEN 600
#define DEPTH  6
#define NCOLS  600
#define NROWPAD 640     // W^T rows padded to 5 tiles of 128

#define KPAD_I 160      // 147 -> 5 chunks of 32
#define KPAD_H 608      // 600 -> 19 chunks
#define KPAD_O 736      // 733 -> 23 chunks

// ---------------- scratch (allocation-free rule: device globals) -----------
__device__ float g_inp [NBONDS * HIDDEN];
__device__ float g_msg [NBONDS * HIDDEN];
__device__ float g_amsg[NATOMS * HIDDEN];
__device__ __nv_bfloat16 g_Ahi[NBONDS * KPAD_O];
__device__ __nv_bfloat16 g_Alo[NBONDS * KPAD_O];
__device__ __nv_bfloat16 g_WiThi[NROWPAD * KPAD_I];
__device__ __nv_bfloat16 g_WiTlo[NROWPAD * KPAD_I];
__device__ __nv_bfloat16 g_WhThi[NROWPAD * KPAD_H];
__device__ __nv_bfloat16 g_WhTlo[NROWPAD * KPAD_H];
__device__ __nv_bfloat16 g_WoThi[NROWPAD * KPAD_O];
__device__ __nv_bfloat16 g_WoTlo[NROWPAD * KPAD_O];

// ---------------- helpers ---------------------------------------------------
__device__ __forceinline__ uint32_t smem_u32(const void* p)
{
    uint32_t a;
    asm("{ .reg .u64 t; cvta.to.shared.u64 t, %1; cvt.u32.u64 %0, t; }"
        : "=r"(a) : "l"(p));
    return a;
}

__device__ __forceinline__ void cp16(uint32_t s, const void* g)
{
    asm volatile("cp.async.cg.shared.global [%0], [%1], 16;"
                 :: "r"(s), "l"(g));
}

__device__ __forceinline__ void cp_commit()
{
    asm volatile("cp.async.commit_group;" ::: "memory");
}

#define LDSM_X4(r0, r1, r2, r3, a) \
    asm volatile("ldmatrix.sync.aligned.m8n8.x4.shared.b16 {%0,%1,%2,%3}, [%4];" \
                 : "=r"(r0), "=r"(r1), "=r"(r2), "=r"(r3) : "r"(a))

#define LDSM_X2(r0, r1, a) \
    asm volatile("ldmatrix.sync.aligned.m8n8.x2.shared.b16 {%0,%1}, [%2];" \
                 : "=r"(r0), "=r"(r1) : "r"(a))

#define MMA_BF16(d, a, b) \
    asm volatile("mma.sync.aligned.m16n8k16.row.col.f32.bf16.bf16.f32 " \
                 "{%0,%1,%2,%3}, {%4,%5,%6,%7}, {%8,%9}, {%0,%1,%2,%3};" \
                 : "+f"((d)[0]), "+f"((d)[1]), "+f"((d)[2]), "+f"((d)[3]) \
                 : "r"((a)[0]), "r"((a)[1]), "r"((a)[2]), "r"((a)[3]), \
                   "r"((b)[0]), "r"((b)[1]))

__device__ __forceinline__ void split2(float v, unsigned short& h, unsigned short& l)
{
    __nv_bfloat16 hb = __float2bfloat16(v);
    float r = v - __bfloat162float(hb);
    __nv_bfloat16 lb = __float2bfloat16(r);
    h = __bfloat16_as_ushort(hb);
    l = __bfloat16_as_ushort(lb);
}

// split 4 floats, pack to uint2 hi / uint2 lo
__device__ __forceinline__ void split4_pack(const float* v, uint2& hv, uint2& lv)
{
    unsigned short h0, h1, h2, h3, l0, l1, l2, l3;
    split2(v[0], h0, l0); split2(v[1], h1, l1);
    split2(v[2], h2, l2); split2(v[3], h3, l3);
    hv.x = (uint32_t)h0 | ((uint32_t)h1 << 16);
    hv.y = (uint32_t)h2 | ((uint32_t)h3 << 16);
    lv.x = (uint32_t)l0 | ((uint32_t)l1 << 16);
    lv.y = (uint32_t)l2 | ((uint32_t)l3 << 16);
}

// ---------------- gather / split kernels ------------------------------------
#define ROW4 (HIDDEN / 4)   // 150

__global__ void gather_sum_kernel(const float4* __restrict__ msg,
                                  const int* __restrict__ a2b,
                                  float4* __restrict__ out)
{
    int tid = blockIdx.x * blockDim.x + threadIdx.x;
    const int total = NATOMS * ROW4;
    if (tid >= total) return;
    int a = tid / ROW4;
    int c = tid - a * ROW4;
    const int* nb = a2b + a * MAXNB;
    float4 s = make_float4(0.f, 0.f, 0.f, 0.f);
#pragma unroll
    for (int j = 0; j < MAXNB; j++) {
        float4 v = msg[(size_t)nb[j] * ROW4 + c];
        s.x += v.x; s.y += v.y; s.z += v.z; s.w += v.w;
    }
    out[(size_t)a * ROW4 + c] = s;
}

// FUSED: msgin[b] = sum_j msg[a2b[b2a[b],j]] - msg[b2revb[b]] -> split hi/lo.
// Skips the amsg materialization entirely (atom rows re-read via L2).
__global__ void fused_msgin_split(const float4* __restrict__ msg,
                                  const int* __restrict__ a2b,
                                  const int* __restrict__ b2a,
                                  const int* __restrict__ b2revb,
                                  __nv_bfloat16* __restrict__ Ahi,
                                  __nv_bfloat16* __restrict__ Alo)
{
    int tid = blockIdx.x * blockDim.x + threadIdx.x;
    const int C4 = KPAD_H / 4;                       // 152
    const int total = NBONDS * C4;
    if (tid >= total) return;
    int b  = tid / C4;
    int c4 = tid - b * C4;
    float d[4] = {0.f, 0.f, 0.f, 0.f};
    if (c4 < ROW4) {
        const int src = b2a[b];
        const int* nb = a2b + (size_t)src * MAXNB;
        float4 s = make_float4(0.f, 0.f, 0.f, 0.f);
#pragma unroll
        for (int j = 0; j < MAXNB; j++) {
            float4 v = msg[(size_t)nb[j] * ROW4 + c4];
            s.x += v.x; s.y += v.y; s.z += v.z; s.w += v.w;
        }
        float4 r = msg[(size_t)b2revb[b] * ROW4 + c4];
        d[0] = s.x - r.x; d[1] = s.y - r.y;
        d[2] = s.z - r.z; d[3] = s.w - r.w;
    }
    uint2 hv, lv;
    split4_pack(d, hv, lv);
    size_t off = (size_t)b * KPAD_H + (size_t)c4 * 4;
    *(uint2*)(Ahi + off) = hv;
    *(uint2*)(Alo + off) = lv;
}

// f_bonds [B,147] -> split, K padded to 160; 4 cols/thread, uint2 stores
__global__ void split_bonds_kernel(const float* __restrict__ fb,
                                   __nv_bfloat16* __restrict__ Ahi,
                                   __nv_bfloat16* __restrict__ Alo)
{
    int tid = blockIdx.x * blockDim.x + threadIdx.x;
    const int C4 = KPAD_I / 4;                       // 40
    const int total = NBONDS * C4;
    if (tid >= total) return;
    int b  = tid / C4;
    int k0 = (tid - b * C4) * 4;
    float v[4];
#pragma unroll
    for (int i = 0; i < 4; i++) {
        int k = k0 + i;
        v[i] = (k < FBOND) ? fb[(size_t)b * FBOND + k] : 0.f;
    }
    uint2 hv, lv;
    split4_pack(v, hv, lv);
    size_t off = (size_t)b * KPAD_I + k0;
    *(uint2*)(Ahi + off) = hv;
    *(uint2*)(Alo + off) = lv;
}

// concat(f_atoms, amsg) -> split, K padded to 736; 4 cols/thread
__global__ void concat_split_kernel(const float* __restrict__ fa,
                                    const float* __restrict__ amsg,
                                    __nv_bfloat16* __restrict__ Ahi,
                                    __nv_bfloat16* __restrict__ Alo)
{
    int tid = blockIdx.x * blockDim.x + threadIdx.x;
    const int C4 = KPAD_O / 4;                       // 184
    const int total = NATOMS * C4;
    if (tid >= total) return;
    int a  = tid / C4;
    int k0 = (tid - a * C4) * 4;
    float v[4];
#pragma unroll
    for (int i = 0; i < 4; i++) {
        int k = k0 + i;
        float x = 0.f;
        if (k < FATOM)               x = fa[(size_t)a * FATOM + k];
        else if (k < FATOM + HIDDEN) x = amsg[(size_t)a * HIDDEN + (k - FATOM)];
        v[i] = x;
    }
    uint2 hv, lv;
    split4_pack(v, hv, lv);
    size_t off = (size_t)a * KPAD_O + k0;
    *(uint2*)(Ahi + off) = hv;
    *(uint2*)(Alo + off) = lv;
}

// W [K,600] row-major -> W^T split bf16, [640][ldT], zero-padded
__global__ void prep_w_kernel(const float* __restrict__ W, int K, int ldT,
                              __nv_bfloat16* __restrict__ Thi,
                              __nv_bfloat16* __restrict__ Tlo)
{
    int tid = blockIdx.x * blockDim.x + threadIdx.x;
    const int total = NROWPAD * ldT;
    if (tid >= total) return;
    int n = tid / ldT;
    int k = tid - n * ldT;
    float v = (n < NCOLS && k < K) ? W[(size_t)k * NCOLS + n] : 0.f;
    unsigned short h, l;
    split2(v, h, l);
    Thi[tid] = __ushort_as_bfloat16(h);
    Tlo[tid] = __ushort_as_bfloat16(l);
}

// ---------------- tensor-core GEMM (mma.sync bf16, split hi/lo) -------------
// grid = (5 N-tiles, ceil(M/128)); 256 threads = 8 warps (4 M x 2 N).
#define RS        40            // smem row stride in bf16 (80B, LDSM-conflict-free)
#define TILE_B    (128 * RS * 2)   // 10240 B
#define OFF_AHI   0
#define OFF_ALO   (TILE_B)
#define OFF_BHI   (2 * TILE_B)
#define OFF_BLO   (3 * TILE_B)
#define STAGE_B   (4 * TILE_B)     // 40960 B
#define SMEM_TOT  (2 * STAGE_B)    // 81920 B

__global__ __launch_bounds__(256)
void gemm_tc(const __nv_bfloat16* __restrict__ Ahi,
             const __nv_bfloat16* __restrict__ Alo,
             const __nv_bfloat16* __restrict__ Bhi,
             const __nv_bfloat16* __restrict__ Blo,
             const float* __restrict__ addend,
             const float* __restrict__ bias,
             float* __restrict__ outRelu,
             float* __restrict__ outPre,
             int M, int KC, int ld)
{
    extern __shared__ char smem[];
    const uint32_t sb = smem_u32(smem);
    const int tid  = threadIdx.x;
    const int lane = tid & 31;
    const int wid  = tid >> 5;
    const int wm   = wid & 3;          // 4 warps along M (32 rows each)
    const int wn   = wid >> 2;         // 2 warps along N (64 cols each)
    const int m0   = blockIdx.y * 128;
    const int n0   = blockIdx.x * 128;

    // async loader: stage s <- K-chunk kc
    auto issue = [&](int kc, int s) {
        const uint32_t sbase = sb + s * STAGE_B;
#pragma unroll
        for (int p = 0; p < 2; p++) {
            int slot = tid + 256 * p;         // 0..511
            int row  = slot >> 2;
            int j    = slot & 3;
            uint32_t soff = (uint32_t)row * (RS * 2) + j * 16;
            int arow = m0 + row;
            if (arow >= M) arow = M - 1;      // clamp (garbage rows masked later)
            size_t ga = (size_t)arow * ld + (size_t)kc * 32 + j * 8;
            cp16(sbase + OFF_AHI + soff, Ahi + ga);
            cp16(sbase + OFF_ALO + soff, Alo + ga);
            size_t gb = (size_t)(n0 + row) * ld + (size_t)kc * 32 + j * 8;
            cp16(sbase + OFF_BHI + soff, Bhi + gb);
            cp16(sbase + OFF_BLO + soff, Blo + gb);
        }
        cp_commit();
    };

    float acc[2][8][4];
#pragma unroll
    for (int mt = 0; mt < 2; mt++)
#pragma unroll
        for (int nt = 0; nt < 8; nt++)
#pragma unroll
            for (int q = 0; q < 4; q++) acc[mt][nt][q] = 0.f;

    issue(0, 0);

    // lane-invariant fragment address pieces
    const int aRow = wm * 32 + (lane & 15);
    const int aCol = (lane >> 4) << 3;
    const int bRow = wn * 64 + (lane & 7);
    const int bCol = ((lane >> 3) & 1) << 3;

    for (int kc = 0; kc < KC; kc++) {
        if (kc + 1 < KC) {
            issue(kc + 1, (kc + 1) & 1);
            asm volatile("cp.async.wait_group 1;" ::: "memory");
        } else {
            asm volatile("cp.async.wait_group 0;" ::: "memory");
        }
        __syncthreads();

        const uint32_t st = sb + (kc & 1) * STAGE_B;
        const uint32_t aAddrBase = st + (uint32_t)aRow * (RS * 2) + aCol * 2;
        const uint32_t bAddrBase = st + (uint32_t)bRow * (RS * 2) + bCol * 2;

#pragma unroll
        for (int ks = 0; ks < 32; ks += 16) {
            uint32_t ahi[2][4], alo[2][4], bfr[8][2];
#pragma unroll
            for (int mt = 0; mt < 2; mt++) {
                uint32_t a = aAddrBase + OFF_AHI + ((uint32_t)mt * 16 * RS + ks) * 2;
                LDSM_X4(ahi[mt][0], ahi[mt][1], ahi[mt][2], ahi[mt][3], a);
            }
#pragma unroll
            for (int nt = 0; nt < 8; nt++) {
                uint32_t b = bAddrBase + OFF_BHI + ((uint32_t)nt * 8 * RS + ks) * 2;
                LDSM_X2(bfr[nt][0], bfr[nt][1], b);
            }
            // product 1: hi * hi
#pragma unroll
            for (int mt = 0; mt < 2; mt++)
#pragma unroll
                for (int nt = 0; nt < 8; nt++)
                    MMA_BF16(acc[mt][nt], ahi[mt], bfr[nt]);
            // product 2: lo * hi
#pragma unroll
            for (int mt = 0; mt < 2; mt++) {
                uint32_t a = aAddrBase + OFF_ALO + ((uint32_t)mt * 16 * RS + ks) * 2;
                LDSM_X4(alo[mt][0], alo[mt][1], alo[mt][2], alo[mt][3], a);
            }
#pragma unroll
            for (int mt = 0; mt < 2; mt++)
#pragma unroll
                for (int nt = 0; nt < 8; nt++)
                    MMA_BF16(acc[mt][nt], alo[mt], bfr[nt]);
            // product 3: hi * lo
#pragma unroll
            for (int nt = 0; nt < 8; nt++) {
                uint32_t b = bAddrBase + OFF_BLO + ((uint32_t)nt * 8 * RS + ks) * 2;
                LDSM_X2(bfr[nt][0], bfr[nt][1], b);
            }
#pragma unroll
            for (int mt = 0; mt < 2; mt++)
#pragma unroll
                for (int nt = 0; nt < 8; nt++)
                    MMA_BF16(acc[mt][nt], ahi[mt], bfr[nt]);
        }
        __syncthreads();
    }

    // epilogue: d-frag thread t -> rows t/4, t/4+8; cols (t%4)*2, +1
    const int rBase = m0 + wm * 32 + (lane >> 2);
    const int cBase = n0 + wn * 64 + (lane & 3) * 2;
#pragma unroll
    for (int mt = 0; mt < 2; mt++) {
#pragma unroll
        for (int half = 0; half < 2; half++) {
            int row = rBase + mt * 16 + half * 8;
            if (row >= M) continue;
            const size_t rb = (size_t)row * NCOLS;
#pragma unroll
            for (int nt = 0; nt < 8; nt++) {
                int col = cBase + nt * 8;
                if (col >= NCOLS) continue;
                float x0 = acc[mt][nt][half * 2 + 0];
                float x1 = acc[mt][nt][half * 2 + 1];
                if (addend) {
                    float2 a = *(const float2*)(addend + rb + col);
                    x0 += a.x; x1 += a.y;
                }
                if (bias) {
                    float2 bv = *(const float2*)(bias + col);
                    x0 += bv.x; x1 += bv.y;
                }
                if (outPre) {
                    float2 pv = make_float2(x0, x1);
                    *(float2*)(outPre + rb + col) = pv;
                }
                float2 rv = make_float2(fmaxf(x0, 0.f), fmaxf(x1, 0.f));
                *(float2*)(outRelu + rb + col) = rv;
            }
        }
    }
}

// ---------------- launch ----------------------------------------------------
static inline int cdiv(int a, int b) { return (a + b - 1) / b; }

extern "C" void kernel_launch(void* const* d_in, const int* in_sizes, int n_in,
                              void* d_out, int out_size)
{
    const float* f_atoms = (const float*)d_in[0];
    const float* f_bonds = (const float*)d_in[1];
    const int*   a2b     = (const int*)d_in[2];
    const int*   b2a     = (const int*)d_in[3];
    const int*   b2revb  = (const int*)d_in[4];
    const float* W_i     = (const float*)d_in[5];
    const float* W_h     = (const float*)d_in[6];
    const float* W_o     = (const float*)d_in[7];
    const float* b_o     = (const float*)d_in[8];
    float*       out     = (float*)d_out;

    float *inp, *msg, *amsg;
    __nv_bfloat16 *Ahi, *Alo, *WiThi, *WiTlo, *WhThi, *WhTlo, *WoThi, *WoTlo;
    cudaGetSymbolAddress((void**)&inp,   g_inp);
    cudaGetSymbolAddress((void**)&msg,   g_msg);
    cudaGetSymbolAddress((void**)&amsg,  g_amsg);
    cudaGetSymbolAddress((void**)&Ahi,   g_Ahi);
    cudaGetSymbolAddress((void**)&Alo,   g_Alo);
    cudaGetSymbolAddress((void**)&WiThi, g_WiThi);
    cudaGetSymbolAddress((void**)&WiTlo, g_WiTlo);
    cudaGetSymbolAddress((void**)&WhThi, g_WhThi);
    cudaGetSymbolAddress((void**)&WhTlo, g_WhTlo);
    cudaGetSymbolAddress((void**)&WoThi, g_WoThi);
    cudaGetSymbolAddress((void**)&WoTlo, g_WoTlo);

    cudaFuncSetAttribute(gemm_tc, cudaFuncAttributeMaxDynamicSharedMemorySize,
                         SMEM_TOT);

    // weight prep (tiny)
    prep_w_kernel<<<cdiv(NROWPAD * KPAD_I, 256), 256>>>(W_i, FBOND, KPAD_I, WiThi, WiTlo);
    prep_w_kernel<<<cdiv(NROWPAD * KPAD_H, 256), 256>>>(W_h, HIDDEN, KPAD_H, WhThi, WhTlo);
    prep_w_kernel<<<cdiv(NROWPAD * KPAD_O, 256), 256>>>(W_o, FATOM + HIDDEN, KPAD_O, WoThi, WoTlo);

    const dim3 gBond(5, cdiv(NBONDS, 128));   // (5, 782) — x fastest: A reuse in L2
    const dim3 gAtom(5, cdiv(NATOMS, 128));   // (5, 391)

    // inp = f_bonds @ W_i ; msg = relu(inp)
    split_bonds_kernel<<<cdiv(NBONDS * (KPAD_I / 4), 256), 256>>>(f_bonds, Ahi, Alo);
    gemm_tc<<<gBond, 256, SMEM_TOT>>>(Ahi, Alo, WiThi, WiTlo,
                                      nullptr, nullptr, msg, inp,
                                      NBONDS, KPAD_I / 32, KPAD_I);

    const int gsBlocks = cdiv(NATOMS * ROW4, 256);
    const int fmBlocks = cdiv(NBONDS * (KPAD_H / 4), 256);

    for (int d = 0; d < DEPTH - 1; d++) {
        // fused: gather 6 neighbors at source atom, subtract reverse, split
        fused_msgin_split<<<fmBlocks, 256>>>((const float4*)msg, a2b, b2a, b2revb,
                                             Ahi, Alo);
        // msg = relu(inp + msgin @ W_h)
        gemm_tc<<<gBond, 256, SMEM_TOT>>>(Ahi, Alo, WhThi, WhTlo,
                                          inp, nullptr, msg, nullptr,
                                          NBONDS, KPAD_H / 32, KPAD_H);
    }

    gather_sum_kernel<<<gsBlocks, 256>>>((const float4*)msg, a2b, (float4*)amsg);
    concat_split_kernel<<<cdiv(NATOMS * (KPAD_O / 4), 256), 256>>>(f_atoms, amsg, Ahi, Alo);
    // out = relu(concat(f_atoms, amsg) @ W_o + b_o)
    gemm_tc<<<gAtom, 256, SMEM_TOT>>>(Ahi, Alo, WoThi, WoTlo,
                                      nullptr, b_o, out, nullptr,
                                      NATOMS, KPAD_O / 32, KPAD_O);
}